// round 15
// baseline (speedup 1.0000x reference)
#include <cuda_runtime.h>
#include <math.h>

#define B_   32
#define C_   128
#define HW_  256
#define V_   8192
#define TOT  (B_*C_*HW_)   // 1048576

typedef unsigned long long u64;

// ---------------- scratch (no allocations allowed) ----------------
__device__ float  g_frest[TOT];
__device__ float  g_restNC[V_*C_];
__device__ float  g_hup[TOT];
__device__ u64    g_keys[V_];
__device__ float  g_esq[V_];
__device__ float  g_W[240];            // W1@0(16), W2@16(32), W4@48(64), W8@112(128)
__device__ float  g_lossPart[5*256];

// ---------------- f32x2 packed helpers ----------------
__device__ __forceinline__ u64 pk2(float lo, float hi){
    u64 r; asm("mov.b64 %0, {%1, %2};" : "=l"(r) : "f"(lo), "f"(hi)); return r;
}
__device__ __forceinline__ void fma2(u64 &d, u64 a, u64 b){
    asm("fma.rn.f32x2 %0, %1, %2, %0;" : "+l"(d) : "l"(a), "l"(b));
}
__device__ __forceinline__ void add2(u64 &d, u64 a){
    asm("add.rn.f32x2 %0, %0, %1;" : "+l"(d) : "l"(a));
}
__device__ __forceinline__ void upk2(float &lo, float &hi, u64 v){
    asm("mov.b64 {%0, %1}, %2;" : "=f"(lo), "=f"(hi) : "l"(v));
}
union F4U { float4 f; u64 u[2]; };

// Keys cubic (a = -0.5), matches jax.image _keys_cubic_kernel
__device__ __forceinline__ double keys_cubic(double x){
    if (x >= 2.0) return 0.0;
    if (x >= 1.0) return ((-0.5*x + 2.5)*x - 4.0)*x + 2.0;
    return ((1.5*x - 2.5)*x)*x + 1.0;
}

// ---------------- merged init + esq ----------------
// blocks [0,8192): esq;  blocks [8192,8704): f_hat=0, f_rest=f, weights, stage0 keys
__global__ void k_init(const float* __restrict__ f, const float* __restrict__ E,
                       float* __restrict__ out){
    int bid = blockIdx.x;
    if (bid < V_){
        __shared__ float r[128];
        int c = threadIdx.x;
        float x = E[bid*C_ + c];
        r[c] = x*x;
        __syncthreads();
        for (int s=64; s>0; s>>=1){
            if (c < s) r[c] += r[c+s];
            __syncthreads();
        }
        if (c==0) g_esq[bid] = r[0];
        return;
    }
    int ib = bid - V_;
    int i = ib*128 + threadIdx.x;
    int stride = 512*128;
    for (; i < TOT; i += stride){ out[i] = 0.f; g_frest[i] = f[i]; }
    if (ib == 0 && threadIdx.x < 32) g_keys[threadIdx.x] = ~0ull;
    if (ib == 0 && threadIdx.x == 0){
        for (int o=0;o<16;o++) g_W[o] = 1.f;
        const int offs[3] = {16,48,112};
        const int pns[3]  = {2,4,8};
        for (int t=0;t<3;t++){
            int pn = pns[t]; int off = offs[t];
            double inv_scale = (double)pn / 16.0;
            for (int o=0;o<16;o++){
                double sf = ((double)o + 0.5) * inv_scale - 0.5;
                double wv[8]; double wsum = 0.0;
                for (int ii=0; ii<pn; ii++){
                    double k = keys_cubic(fabs(sf - (double)ii));
                    wv[ii] = k; wsum += k;
                }
                for (int ii=0; ii<pn; ii++)
                    g_W[off + o*pn + ii] = (float)(wv[ii]/wsum);
            }
        }
    }
}

// ---------------- area pool (stage 0 only) ----------------
__global__ void k_pool(int pn){
    __shared__ float s[256];
    int bc = blockIdx.x;           // b*128 + c
    int b = bc >> 7, c = bc & 127;
    int tid = threadIdx.x;
    s[tid] = g_frest[bc*256 + tid];
    __syncthreads();
    int S = 16/pn;
    if (tid < pn*pn){
        int i = tid / pn, j = tid - i*pn;
        float sum = 0.f;
        for (int dh=0; dh<S; dh++)
            for (int dw=0; dw<S; dw++)
                sum += s[(i*S+dh)*16 + j*S + dw];
        g_restNC[(b*pn*pn + tid)*C_ + c] = sum * (1.f/(float)(S*S));
    }
}

// ---------------- small argmin: 32 rows x 128 v tiles (stages 0-1) ----------------
__global__ __launch_bounds__(256) void k_argmin_s(const float* __restrict__ E, int vchunk){
    __shared__ float sA[128*33];          // [k][row], padded
    __shared__ float sB[16][128];
    __shared__ u64 sMin[32];
    int tid = threadIdx.x;
    int n0 = blockIdx.x * 32;
    int v0base = blockIdx.y * vchunk;

    {
        int r = tid >> 3, q = tid & 7;
#pragma unroll
        for (int i=0;i<4;i++){
            int c0 = q*4 + i*32;
            float4 v = *(const float4*)&g_restNC[(size_t)(n0+r)*C_ + c0];
            sA[(c0+0)*33 + r] = v.x;
            sA[(c0+1)*33 + r] = v.y;
            sA[(c0+2)*33 + r] = v.z;
            sA[(c0+3)*33 + r] = v.w;
        }
    }
    if (tid < 32) sMin[tid] = ~0ull;

    int tx = tid & 15, ty = tid >> 4;
    int r0 = ty*2;
    int lrow = tid >> 1, lkof = (tid & 1) << 3;
    u64 best[2] = {~0ull, ~0ull};

    int nvt = vchunk >> 7;
    for (int vt = 0; vt < nvt; vt++){
        int v0 = v0base + vt*128;
        const float* bptr = E + (size_t)(v0+lrow)*C_ + lkof;
        u64 acc2[2][4];
#pragma unroll
        for (int i=0;i<2;i++)
#pragma unroll
            for (int j=0;j<4;j++) acc2[i][j]=0ull;

#pragma unroll
        for (int kt=0; kt<8; kt++){
            int k0 = kt*16;
            float4 b0 = *(const float4*)(bptr + k0);
            float4 b1 = *(const float4*)(bptr + k0 + 4);
            __syncthreads();
            sB[lkof+0][lrow]=b0.x; sB[lkof+1][lrow]=b0.y; sB[lkof+2][lrow]=b0.z; sB[lkof+3][lrow]=b0.w;
            sB[lkof+4][lrow]=b1.x; sB[lkof+5][lrow]=b1.y; sB[lkof+6][lrow]=b1.z; sB[lkof+7][lrow]=b1.w;
            __syncthreads();
#pragma unroll
            for (int kk=0;kk<16;kk++){
                int kg = k0 + kk;
                float a0 = sA[kg*33 + r0];
                float a1 = sA[kg*33 + r0 + 1];
                u64 aB0 = pk2(a0,a0), aB1 = pk2(a1,a1);
                F4U bv0, bv1;
                bv0.f = *(const float4*)&sB[kk][tx*8];
                bv1.f = *(const float4*)&sB[kk][tx*8+4];
                u64 bp[4] = {bv0.u[0], bv0.u[1], bv1.u[0], bv1.u[1]};
#pragma unroll
                for (int j=0;j<4;j++){ fma2(acc2[0][j], aB0, bp[j]); fma2(acc2[1][j], aB1, bp[j]); }
            }
        }
#pragma unroll
        for (int j2=0;j2<4;j2++){
            int ve = v0 + tx*8 + j2*2;
            float eqe = g_esq[ve], eqo = g_esq[ve+1];
#pragma unroll
            for (int i=0;i<2;i++){
                float lo, hi; upk2(lo, hi, acc2[i][j2]);
                float se = fmaf(-2.f, lo, eqe);
                float so = fmaf(-2.f, hi, eqo);
                unsigned ue = __float_as_uint(se); ue = (ue & 0x80000000u) ? ~ue : (ue | 0x80000000u);
                unsigned uo = __float_as_uint(so); uo = (uo & 0x80000000u) ? ~uo : (uo | 0x80000000u);
                u64 ke = ((u64)ue << 32) | (u64)(unsigned)ve;
                u64 ko = ((u64)uo << 32) | (u64)(unsigned)(ve+1);
                if (ke < best[i]) best[i] = ke;
                if (ko < best[i]) best[i] = ko;
            }
        }
    }
    __syncthreads();
    atomicMin(&sMin[r0],   best[0]);
    atomicMin(&sMin[r0+1], best[1]);
    __syncthreads();
    if (tid < 32) atomicMin(&g_keys[n0+tid], sMin[tid]);
}

// ---------------- big argmin: 128 rows resident, dup-B smem, f32x2 core ----------------
// mode 0: rows from g_restNC; mode 1: rows directly from g_frest (last stage)
#define SA_PITCH 132
#define BD_PITCH 17   // u64 pitch of dup-B (kk,j) rows -> conflict-free LDS.64
__global__ __launch_bounds__(256,2) void k_argmin_b(const float* __restrict__ E, int vchunk, int mode){
    extern __shared__ float dyn[];
    float* sA  = dyn;                                  // [128 k][132 rows] floats
    u64*  sBd = (u64*)(dyn + 128*SA_PITCH);            // [2][16*8*17] u64 dup pairs
    u64*  sMin = sBd + 2*16*8*BD_PITCH;

    int tid = threadIdx.x;
    int n0 = blockIdx.x * 128;
    int v0base = blockIdx.y * vchunk;

    if (mode == 0){
        int r = tid >> 1, ch = (tid & 1) * 64;
        const float* src = g_restNC + (size_t)(n0+r)*C_ + ch;
#pragma unroll
        for (int i=0;i<16;i++){
            int c0 = ch + i*4;
            float4 v = *(const float4*)(src + i*4);
            sA[(c0+0)*SA_PITCH + r] = v.x;
            sA[(c0+1)*SA_PITCH + r] = v.y;
            sA[(c0+2)*SA_PITCH + r] = v.z;
            sA[(c0+3)*SA_PITCH + r] = v.w;
        }
    } else {
        int c = tid >> 1, ph = (tid & 1) * 64;
        int b = n0 >> 8, pix0 = n0 & 255;
        const float* src = g_frest + ((size_t)(b*C_ + c))*HW_ + pix0;
#pragma unroll
        for (int i=0;i<16;i++){
            int p = ph + i*4;
            float4 v = *(const float4*)(src + p);
            *(float4*)&sA[c*SA_PITCH + p] = v;
        }
    }
    if (tid < 128) sMin[tid] = ~0ull;

    int tx = tid & 15, ty = tid >> 4;
    int lrow = tid >> 1, lkof = (tid & 1) << 3;
    int jrow = lrow & 7, txs = lrow >> 3;              // producer dup-store coords
    u64 best[8];
#pragma unroll
    for (int i=0;i<8;i++) best[i] = ~0ull;

    int nvt = vchunk >> 7;
    for (int vt = 0; vt < nvt; vt++){
        int v0 = v0base + vt*128;
        const float* bptr = E + (size_t)(v0+lrow)*C_ + lkof;
        u64 acc2[4][8];
#pragma unroll
        for (int i=0;i<4;i++)
#pragma unroll
            for (int j=0;j<8;j++) acc2[i][j]=0ull;

        float4 b0 = *(const float4*)(bptr);
        float4 b1 = *(const float4*)(bptr + 4);
#pragma unroll
        for (int kt=0; kt<8; kt++){
            u64* sbb = sBd + (kt&1)*(16*8*BD_PITCH);
            {
                float bv[8] = {b0.x,b0.y,b0.z,b0.w,b1.x,b1.y,b1.z,b1.w};
#pragma unroll
                for (int i=0;i<8;i++)
                    sbb[((lkof+i)*8 + jrow)*BD_PITCH + txs] = pk2(bv[i], bv[i]);
            }
            __syncthreads();
            if (kt < 7){
                int k0 = (kt+1)*16;
                b0 = *(const float4*)(bptr + k0);
                b1 = *(const float4*)(bptr + k0 + 4);
            }
#pragma unroll
            for (int kk=0;kk<16;kk++){
                int kg = kt*16 + kk;
                F4U av0, av1;
                av0.f = *(const float4*)&sA[kg*SA_PITCH + ty*8];
                av1.f = *(const float4*)&sA[kg*SA_PITCH + ty*8 + 4];
                u64 ap[4] = {av0.u[0], av0.u[1], av1.u[0], av1.u[1]};   // row pairs
                const u64* bb = sbb + (kk*8)*BD_PITCH + tx;
                u64 bB[8];
#pragma unroll
                for (int j=0;j<8;j++) bB[j] = bb[j*BD_PITCH];           // dup v pairs
#pragma unroll
                for (int i2=0;i2<4;i2++)
#pragma unroll
                    for (int j=0;j<8;j++) fma2(acc2[i2][j], ap[i2], bB[j]);
            }
        }
#pragma unroll
        for (int j=0;j<8;j++){
            int v = v0 + tx*8 + j;
            float eq = g_esq[v];
#pragma unroll
            for (int i2=0;i2<4;i2++){
                float lo, hi; upk2(lo, hi, acc2[i2][j]);
                float se = fmaf(-2.f, lo, eq);
                float so = fmaf(-2.f, hi, eq);
                unsigned ue = __float_as_uint(se); ue = (ue & 0x80000000u) ? ~ue : (ue | 0x80000000u);
                unsigned uo = __float_as_uint(so); uo = (uo & 0x80000000u) ? ~uo : (uo | 0x80000000u);
                u64 ke = ((u64)ue << 32) | (u64)(unsigned)v;
                u64 ko = ((u64)uo << 32) | (u64)(unsigned)v;
                if (ke < best[2*i2])   best[2*i2]   = ke;
                if (ko < best[2*i2+1]) best[2*i2+1] = ko;
            }
        }
    }
    __syncthreads();
#pragma unroll
    for (int i=0;i<8;i++) atomicMin(&sMin[ty*8+i], best[i]);
    __syncthreads();
    if (tid < 128) atomicMin(&g_keys[n0+tid], sMin[tid]);
}

// ---------------- staged gather for pn in {1,2,4,8} ----------------
__global__ __launch_bounds__(256) void k_gather_s(const float* __restrict__ E, int pn, int woff){
    __shared__ float sE[64][16];
    __shared__ int sIdx[64];
    int b = blockIdx.x, cg = blockIdx.y;
    int c0 = cg*16;
    int tid = threadIdx.x;
    int nn = pn*pn;
    if (tid < nn) sIdx[tid] = (int)(unsigned)(g_keys[b*nn + tid]);
    __syncthreads();
    for (int r0 = 0; r0 < nn; r0 += 16){
        int r = r0 + (tid >> 4), cl = tid & 15;
        if (r < nn) sE[r][cl] = E[(size_t)sIdx[r]*C_ + c0 + cl];
    }
    __syncthreads();
    int pix = tid, o1 = pix >> 4, o2 = pix & 15;
#pragma unroll 4
    for (int c=0;c<16;c++){
        float acc = 0.f;
        for (int i1=0;i1<pn;i1++){
            float w1 = g_W[woff + o1*pn + i1];
            if (w1 == 0.f) continue;
            for (int i2=0;i2<pn;i2++){
                float w2 = g_W[woff + o2*pn + i2];
                if (w2 == 0.f) continue;
                acc = fmaf(w1*w2, sE[i1*pn+i2][c], acc);
            }
        }
        g_hup[((size_t)b*C_ + c0 + c)*HW_ + pix] = acc;
    }
}

// ---------------- direct gather for pn=16 ----------------
__global__ void k_gather(const float* __restrict__ E){
    int bp = blockIdx.x; int b = bp >> 8; int pix = bp & 255;
    int c = threadIdx.x;   // 128
    int v = (int)(unsigned)(g_keys[b*256 + pix]);
    g_hup[(b*C_ + c)*HW_ + pix] = E[(size_t)v*C_ + c];
}

// ---------------- conv3x3 + Phi + updates + fused next-stage pool + key init ------
// grid (B=32, 8 oc-groups of 16), 256 threads (16 ocl x 16 h).
// sInS holds shifted rows [0, r0..r15, 0] so Ep pairs load via aligned LDS.64.
__global__ __launch_bounds__(256,2) void k_conv(
    const float* __restrict__ phiw, const float* __restrict__ phib,
    const float* __restrict__ f, float* __restrict__ fhat,
    int kphi, int si, int Nn, int pn_next)
{
    __shared__ __align__(16) float sIn[16][256];       // reused as sPool at end
    __shared__ __align__(8)  float sInS[16][16][18];
    __shared__ __align__(16) float sW[16][16][12];
    __shared__ float sRed[256];
    int b = blockIdx.x, ocg = blockIdx.y;
    int tid = threadIdx.x;
    int ocl = tid >> 4, h = tid & 15;
    int oc = ocg*16 + ocl;

    if (Nn > 0){
        int flat = b*8 + ocg;                 // 0..255
        int per = (Nn + 255) >> 8;
        if (tid < per){
            int ki = flat*per + tid;
            if (ki < Nn) g_keys[ki] = ~0ull;
        }
    }
    // zero sInS halo once (positions 0 and 17 of each row; never overwritten)
    { int t = tid >> 4, hr = tid & 15; sInS[t][hr][0] = 0.f; sInS[t][hr][17] = 0.f; }

    u64 acc2[8];
#pragma unroll
    for (int m=0;m<8;m++) acc2[m]=0ull;

    const float* inb = g_hup + (size_t)b*C_*HW_;
    int sh = tid >> 4, sx = tid & 15;       // pixel -> (row, col) for sInS staging
    for (int icc=0; icc<128; icc+=16){
#pragma unroll
        for (int t=0;t<16;t++){
            float v = inb[(icc+t)*HW_ + tid];
            sIn[t][tid] = v;
            sInS[t][sh][sx+1] = v;
        }
        {
            const float* wp = phiw + (((size_t)kphi*C_ + oc)*C_ + (icc + h))*9;
#pragma unroll
            for (int k=0;k<9;k++) sW[h][ocl][k] = wp[k];
        }
        __syncthreads();
        for (int ic=0; ic<16; ic++){
            float4 wa = *(const float4*)&sW[ic][ocl][0];
            float4 wb = *(const float4*)&sW[ic][ocl][4];
            float w8 = sW[ic][ocl][8];
            float wf[9] = {wa.x,wa.y,wa.z,wa.w,wb.x,wb.y,wb.z,wb.w,w8};
            u64 w2[9];
#pragma unroll
            for (int t=0;t<9;t++) w2[t] = pk2(wf[t], wf[t]);

            u64 s2[8];
#pragma unroll
            for (int m=0;m<8;m++) s2[m]=0ull;

#pragma unroll
            for (int dh=0; dh<3; dh++){
                int hh = h + dh - 1;
                u64 O[8], Ep[9];
                if (hh >= 0 && hh < 16){
                    F4U l0,l1,l2,l3;
                    const float4* rp = (const float4*)&sIn[ic][hh*16];
                    l0.f = rp[0]; l1.f = rp[1]; l2.f = rp[2]; l3.f = rp[3];
                    O[0]=l0.u[0]; O[1]=l0.u[1]; O[2]=l1.u[0]; O[3]=l1.u[1];
                    O[4]=l2.u[0]; O[5]=l2.u[1]; O[6]=l3.u[0]; O[7]=l3.u[1];
                    const u64* ep = (const u64*)&sInS[ic][hh][0];
#pragma unroll
                    for (int m=0;m<9;m++) Ep[m] = ep[m];
                } else {
#pragma unroll
                    for (int m=0;m<8;m++) O[m]=0ull;
#pragma unroll
                    for (int m=0;m<9;m++) Ep[m]=0ull;
                }
#pragma unroll
                for (int m=0;m<8;m++){
                    fma2(s2[m], Ep[m],   w2[dh*3+0]);   // dw=0
                    fma2(s2[m], O[m],    w2[dh*3+1]);   // dw=1
                    fma2(s2[m], Ep[m+1], w2[dh*3+2]);   // dw=2
                }
            }
#pragma unroll
            for (int m=0;m<8;m++) add2(acc2[m], s2[m]);
        }
        __syncthreads();
    }

    float acc[16];
#pragma unroll
    for (int m=0;m<8;m++) upk2(acc[2*m], acc[2*m+1], acc2[m]);

    float bias = phib[kphi*C_ + oc];
    int base = (b*C_ + oc)*HW_ + h*16;
    float* sPool = &sIn[0][0];              // alias: sIn free after last sync
    float lsum = 0.f;
#pragma unroll
    for (int x=0;x<16;x++){
        float y  = acc[x] + bias;
        float hi = g_hup[base + x];
        float hp = 0.5f*hi + 0.5f*y;          // Phi: x*(1-r) + conv(x)*r, r=0.5
        float fh = fhat[base + x] + hp;
        fhat[base + x] = fh;
        float fr = g_frest[base + x] - hp;    // bit-identical RMW
        g_frest[base + x] = fr;
        sPool[ocl*256 + h*16 + x] = fr;
        float d = fh - f[base + x];
        lsum = fmaf(d, d, lsum);
    }
    sRed[tid] = lsum;
    __syncthreads();
    for (int s=128; s>0; s>>=1){
        if (tid < s) sRed[tid] += sRed[tid+s];
        __syncthreads();
    }
    if (tid == 0) g_lossPart[si*256 + ocg*32 + b] = sRed[0];

    // fused pool for next stage (exact k_pool summation order)
    if (pn_next > 0){
        int S = 16/pn_next, nn = pn_next*pn_next;
        for (int o = tid; o < 16*nn; o += 256){
            int ocl2 = o / nn; int p = o - ocl2*nn;
            int i = p / pn_next, j = p - i*pn_next;
            const float* sp = sPool + ocl2*256;
            float sum = 0.f;
            for (int dh=0; dh<S; dh++)
                for (int dw=0; dw<S; dw++)
                    sum += sp[(i*S+dh)*16 + j*S + dw];
            g_restNC[((size_t)b*nn + p)*C_ + (ocg*16 + ocl2)] = sum * (1.f/(float)(S*S));
        }
    }
}

// ---------------- loss finalize (deterministic, double) ----------------
__global__ void k_final(float* out){
    if (threadIdx.x == 0){
        double total = 0.0;
        for (int s=0;s<5;s++){
            double m = 0.0;
            for (int i=0;i<256;i++) m += (double)g_lossPart[s*256+i];
            total += 1.25 * (m / (double)TOT);   // (1+BETA)*mean
        }
        out[TOT] = (float)(total / 5.0);          // / SN
    }
}

// ---------------- launch ----------------
extern "C" void kernel_launch(void* const* d_in, const int* in_sizes, int n_in,
                              void* d_out, int out_size){
    (void)in_sizes; (void)n_in; (void)out_size;
    const float* f  = (const float*)d_in[0];
    const float* E  = (const float*)d_in[1];
    const float* pw = (const float*)d_in[2];
    const float* pb = (const float*)d_in[3];
    float* out = (float*)d_out;

    // replicate np.linspace(1/12, 11/12, 4) + argmin tick selection in double
    double start = 1.0/12.0, stop = 1.0 - 1.0/12.0;
    double step = (stop - start) / 3.0;
    double ticks[4];
    for (int i=0;i<4;i++) ticks[i] = (double)i*step + start;
    ticks[3] = stop;
    int kphi[5];
    for (int si=0;si<5;si++){
        double t = (double)si / 4.0;
        int best = 0;
        for (int k=1;k<4;k++)
            if (fabs(ticks[k]-t) < fabs(ticks[best]-t)) best = k;
        kphi[si] = best;
    }

    const int DYNSZ = 128*SA_PITCH*4 + 2*16*8*BD_PITCH*8 + 128*8;   // 103424 bytes
    cudaFuncSetAttribute(k_argmin_b, cudaFuncAttributeMaxDynamicSharedMemorySize, DYNSZ);

    k_init<<<V_ + 512, 128>>>(f, E, out);

    // stage 0: pn=1, N=32
    k_pool<<<B_*C_, 256>>>(1);
    k_argmin_s<<<dim3(1,64), 256>>>(E, 128);
    k_gather_s<<<dim3(B_,8), 256>>>(E, 1, 0);
    k_conv<<<dim3(B_,8), 256>>>(pw, pb, f, out, kphi[0], 0, 128, 2);

    // stage 1: pn=2, N=128
    k_argmin_s<<<dim3(4,64), 256>>>(E, 128);
    k_gather_s<<<dim3(B_,8), 256>>>(E, 2, 16);
    k_conv<<<dim3(B_,8), 256>>>(pw, pb, f, out, kphi[1], 1, 512, 4);

    // stage 2: pn=4, N=512
    k_argmin_b<<<dim3(4,64), 256, DYNSZ>>>(E, 128, 0);
    k_gather_s<<<dim3(B_,8), 256>>>(E, 4, 48);
    k_conv<<<dim3(B_,8), 256>>>(pw, pb, f, out, kphi[2], 2, 2048, 8);

    // stage 3: pn=8, N=2048
    k_argmin_b<<<dim3(16,16), 256, DYNSZ>>>(E, 512, 0);
    k_gather_s<<<dim3(B_,8), 256>>>(E, 8, 112);
    k_conv<<<dim3(B_,8), 256>>>(pw, pb, f, out, kphi[3], 3, 8192, 0);  // keys for s4; s4 pools nothing

    // stage 4: pn=16, N=8192 (rows directly from g_frest)
    k_argmin_b<<<dim3(64,4), 256, DYNSZ>>>(E, 2048, 1);
    k_gather<<<B_*HW_, 128>>>(E);
    k_conv<<<dim3(B_,8), 256>>>(pw, pb, f, out, kphi[4], 4, 0, 0);

    k_final<<<1, 32>>>(out);
}

// round 16
// speedup vs baseline: 1.2427x; 1.2427x over previous
#include <cuda_runtime.h>
#include <math.h>

#define B_   32
#define C_   128
#define HW_  256
#define V_   8192
#define TOT  (B_*C_*HW_)   // 1048576

typedef unsigned long long u64;

// ---------------- scratch (no allocations allowed) ----------------
__device__ float  g_frest[TOT];
__device__ float  g_restNC[V_*C_];
__device__ float  g_hup[TOT];
__device__ u64    g_keys[V_];
__device__ float  g_esq[V_];
__device__ float  g_W[240];            // W1@0(16), W2@16(32), W4@48(64), W8@112(128)
__device__ float  g_lossPart[5*256];
// tf32-split codebook in mma-fragment order: idx = ((kt*1024 + jg)*32 + lane)*2 + slot
__device__ float  g_EswH[16*1024*64];  // 4MB
__device__ float  g_EswL[16*1024*64];  // 4MB

// ---------------- f32x2 packed helpers ----------------
__device__ __forceinline__ u64 pk2(float lo, float hi){
    u64 r; asm("mov.b64 %0, {%1, %2};" : "=l"(r) : "f"(lo), "f"(hi)); return r;
}
__device__ __forceinline__ void fma2(u64 &d, u64 a, u64 b){
    asm("fma.rn.f32x2 %0, %1, %2, %0;" : "+l"(d) : "l"(a), "l"(b));
}
__device__ __forceinline__ void add2(u64 &d, u64 a){
    asm("add.rn.f32x2 %0, %0, %1;" : "+l"(d) : "l"(a));
}
__device__ __forceinline__ void upk2(float &lo, float &hi, u64 v){
    asm("mov.b64 {%0, %1}, %2;" : "=f"(lo), "=f"(hi) : "l"(v));
}
union F4U { float4 f; u64 u[2]; };

__device__ __forceinline__ unsigned tf32r(float x){
    unsigned r; asm("cvt.rna.tf32.f32 %0, %1;" : "=r"(r) : "f"(x)); return r;
}
__device__ __forceinline__ u64 mkkey(float s, int v){
    unsigned u = __float_as_uint(s);
    u = (u & 0x80000000u) ? ~u : (u | 0x80000000u);
    return ((u64)u << 32) | (u64)(unsigned)v;
}

#define MMA4(c, a0,a1,a2,a3, b0,b1) \
    asm("mma.sync.aligned.m16n8k8.row.col.f32.tf32.tf32.f32 " \
        "{%0,%1,%2,%3},{%4,%5,%6,%7},{%8,%9},{%0,%1,%2,%3};" \
        : "+f"(c[0]),"+f"(c[1]),"+f"(c[2]),"+f"(c[3]) \
        : "r"(a0),"r"(a1),"r"(a2),"r"(a3),"r"(b0),"r"(b1))

// Keys cubic (a = -0.5), matches jax.image _keys_cubic_kernel
__device__ __forceinline__ double keys_cubic(double x){
    if (x >= 2.0) return 0.0;
    if (x >= 1.0) return ((-0.5*x + 2.5)*x - 4.0)*x + 2.0;
    return ((1.5*x - 2.5)*x)*x + 1.0;
}

// ---------------- init: f_hat=0, f_rest=f, bicubic weights, stage0 keys ----------------
__global__ void k_init(const float* __restrict__ f, float* __restrict__ out){
    int i = blockIdx.x*blockDim.x + threadIdx.x;
    int stride = gridDim.x*blockDim.x;
    for (; i < TOT; i += stride){ out[i] = 0.f; g_frest[i] = f[i]; }
    if (blockIdx.x == 0 && threadIdx.x < 32) g_keys[threadIdx.x] = ~0ull;
    if (blockIdx.x == 0 && threadIdx.x == 0){
        for (int o=0;o<16;o++) g_W[o] = 1.f;
        const int offs[3] = {16,48,112};
        const int pns[3]  = {2,4,8};
        for (int t=0;t<3;t++){
            int pn = pns[t]; int off = offs[t];
            double inv_scale = (double)pn / 16.0;
            for (int o=0;o<16;o++){
                double sf = ((double)o + 0.5) * inv_scale - 0.5;
                double wv[8]; double wsum = 0.0;
                for (int ii=0; ii<pn; ii++){
                    double k = keys_cubic(fabs(sf - (double)ii));
                    wv[ii] = k; wsum += k;
                }
                for (int ii=0; ii<pn; ii++)
                    g_W[off + o*pn + ii] = (float)(wv[ii]/wsum);
            }
        }
    }
}

// ---------------- ||e||^2 ----------------
__global__ void k_esq(const float* __restrict__ E){
    __shared__ float r[128];
    int v = blockIdx.x, c = threadIdx.x;
    float x = E[v*C_ + c];
    r[c] = x*x;
    __syncthreads();
    for (int s=64; s>0; s>>=1){
        if (c < s) r[c] += r[c+s];
        __syncthreads();
    }
    if (c==0) g_esq[v] = r[0];
}

// ---------------- codebook tf32 split -> fragment-order layout ----------------
__global__ void k_split(const float* __restrict__ E){
    int idx = blockIdx.x*256 + threadIdx.x;     // 0 .. 1048575
    int slot = idx & 1;
    int lane = (idx >> 1) & 31;
    int jg   = (idx >> 6) & 1023;
    int kt   = idx >> 16;
    int v = jg*8 + (lane>>2);
    int k = kt*8 + (lane&3) + slot*4;
    float a = E[v*C_ + k];
    unsigned hb = tf32r(a);
    float ah = __uint_as_float(hb);
    float al = a - ah;
    g_EswH[idx] = ah;
    g_EswL[idx] = __uint_as_float(tf32r(al));
}

// ---------------- area pool f_rest -> rest_NC [N][C] ----------------
__global__ void k_pool(int pn){
    __shared__ float s[256];
    int bc = blockIdx.x;           // b*128 + c
    int b = bc >> 7, c = bc & 127;
    int tid = threadIdx.x;
    s[tid] = g_frest[bc*256 + tid];
    __syncthreads();
    int S = 16/pn;
    if (tid < pn*pn){
        int i = tid / pn, j = tid - i*pn;
        float sum = 0.f;
        for (int dh=0; dh<S; dh++)
            for (int dw=0; dw<S; dw++)
                sum += s[(i*S+dh)*16 + j*S + dw];
        g_restNC[(b*pn*pn + tid)*C_ + c] = sum * (1.f/(float)(S*S));
    }
}

// ---------------- small argmin: 32 rows x 128 v tiles (stages 0-1) ----------------
__global__ __launch_bounds__(256) void k_argmin_s(const float* __restrict__ E, int vchunk){
    __shared__ float sA[128*33];          // [k][row], padded
    __shared__ float sB[16][128];
    __shared__ u64 sMin[32];
    int tid = threadIdx.x;
    int n0 = blockIdx.x * 32;
    int v0base = blockIdx.y * vchunk;

    {
        int r = tid >> 3, q = tid & 7;
#pragma unroll
        for (int i=0;i<4;i++){
            int c0 = q*4 + i*32;
            float4 v = *(const float4*)&g_restNC[(size_t)(n0+r)*C_ + c0];
            sA[(c0+0)*33 + r] = v.x;
            sA[(c0+1)*33 + r] = v.y;
            sA[(c0+2)*33 + r] = v.z;
            sA[(c0+3)*33 + r] = v.w;
        }
    }
    if (tid < 32) sMin[tid] = ~0ull;

    int tx = tid & 15, ty = tid >> 4;
    int r0 = ty*2;
    int lrow = tid >> 1, lkof = (tid & 1) << 3;
    u64 best[2] = {~0ull, ~0ull};

    int nvt = vchunk >> 7;
    for (int vt = 0; vt < nvt; vt++){
        int v0 = v0base + vt*128;
        const float* bptr = E + (size_t)(v0+lrow)*C_ + lkof;
        u64 acc2[2][4];
#pragma unroll
        for (int i=0;i<2;i++)
#pragma unroll
            for (int j=0;j<4;j++) acc2[i][j]=0ull;

#pragma unroll
        for (int kt=0; kt<8; kt++){
            int k0 = kt*16;
            float4 b0 = *(const float4*)(bptr + k0);
            float4 b1 = *(const float4*)(bptr + k0 + 4);
            __syncthreads();
            sB[lkof+0][lrow]=b0.x; sB[lkof+1][lrow]=b0.y; sB[lkof+2][lrow]=b0.z; sB[lkof+3][lrow]=b0.w;
            sB[lkof+4][lrow]=b1.x; sB[lkof+5][lrow]=b1.y; sB[lkof+6][lrow]=b1.z; sB[lkof+7][lrow]=b1.w;
            __syncthreads();
#pragma unroll
            for (int kk=0;kk<16;kk++){
                int kg = k0 + kk;
                float a0 = sA[kg*33 + r0];
                float a1 = sA[kg*33 + r0 + 1];
                u64 aB0 = pk2(a0,a0), aB1 = pk2(a1,a1);
                F4U bv0, bv1;
                bv0.f = *(const float4*)&sB[kk][tx*8];
                bv1.f = *(const float4*)&sB[kk][tx*8+4];
                u64 bp[4] = {bv0.u[0], bv0.u[1], bv1.u[0], bv1.u[1]};
#pragma unroll
                for (int j=0;j<4;j++){ fma2(acc2[0][j], aB0, bp[j]); fma2(acc2[1][j], aB1, bp[j]); }
            }
        }
#pragma unroll
        for (int j2=0;j2<4;j2++){
            int ve = v0 + tx*8 + j2*2;
            float eqe = g_esq[ve], eqo = g_esq[ve+1];
#pragma unroll
            for (int i=0;i<2;i++){
                float lo, hi; upk2(lo, hi, acc2[i][j2]);
                float se = fmaf(-2.f, lo, eqe);
                float so = fmaf(-2.f, hi, eqo);
                u64 ke = mkkey(se, ve);
                u64 ko = mkkey(so, ve+1);
                if (ke < best[i]) best[i] = ke;
                if (ko < best[i]) best[i] = ko;
            }
        }
    }
    __syncthreads();
    atomicMin(&sMin[r0],   best[0]);
    atomicMin(&sMin[r0+1], best[1]);
    __syncthreads();
    if (tid < 32) atomicMin(&g_keys[n0+tid], sMin[tid]);
}

// ---------------- tensor-core argmin: 64 rows/block, 3xTF32 mma ----------------
// mode 0: rows from g_restNC[n][c]; mode 1: rows directly from g_frest (stage 4)
#define TP 132
__global__ __launch_bounds__(256,2) void k_argmin_t(int vchunk, int mode){
    extern __shared__ float dyn2[];
    float* sAh = dyn2;                    // [64][TP]
    float* sAl = dyn2 + 64*TP;
    float* sBH = dyn2 + 128*TP;           // [2][1024]
    float* sBL = sBH + 2048;
    u64*  sMin = (u64*)(sBL + 2048);      // [64]

    int tid = threadIdx.x;
    int n0 = blockIdx.x * 64;
    int v0base = blockIdx.y * vchunk;

    // ---- stage A (64 rows x 128 k), tf32-split, padded ----
    if (mode == 0){
        int r = tid >> 2, cs = (tid & 3) * 32;
        const float* s = g_restNC + (size_t)(n0+r)*C_ + cs;
#pragma unroll
        for (int i=0;i<8;i++){
            float4 v4 = *(const float4*)(s + i*4);
            float vv[4] = {v4.x, v4.y, v4.z, v4.w};
#pragma unroll
            for (int e=0;e<4;e++){
                float a = vv[e];
                float ah = __uint_as_float(tf32r(a));
                float al = a - ah;
                sAh[r*TP + cs + i*4 + e] = ah;
                sAl[r*TP + cs + i*4 + e] = __uint_as_float(tf32r(al));
            }
        }
    } else {
        int c = tid >> 1, rh2 = (tid & 1) * 32;
        int b = n0 >> 8, pix0 = n0 & 255;
        const float* s = g_frest + ((size_t)(b*C_ + c))*HW_ + pix0 + rh2;
#pragma unroll
        for (int i=0;i<8;i++){
            float4 v4 = *(const float4*)(s + i*4);
            float vv[4] = {v4.x, v4.y, v4.z, v4.w};
#pragma unroll
            for (int e=0;e<4;e++){
                int row = rh2 + i*4 + e;
                float a = vv[e];
                float ah = __uint_as_float(tf32r(a));
                float al = a - ah;
                sAh[row*TP + c] = ah;
                sAl[row*TP + c] = __uint_as_float(tf32r(al));
            }
        }
    }
    if (tid < 64) sMin[tid] = ~0ull;
    __syncthreads();

    int lane = tid & 31, w = tid >> 5;
    int q = lane & 3, g = lane >> 2;
    int wr = (w & 3) * 16;      // warp row base (0,16,32,48)
    int vh = w >> 5 ? 0 : (w >> 2);  // v-half 0/1
    vh = w >> 2;
    u64 best0 = ~0ull, best1 = ~0ull;   // rows wr+g, wr+g+8

    int nvt = vchunk >> 7;
    for (int vt = 0; vt < nvt; vt++){
        int v0 = v0base + vt*128;
        size_t bbase = (size_t)(v0 >> 3) * 64;   // jg0*64 floats

        float acc[8][4];
#pragma unroll
        for (int j=0;j<8;j++){ acc[j][0]=0.f; acc[j][1]=0.f; acc[j][2]=0.f; acc[j][3]=0.f; }

        float4 rH = *(const float4*)(g_EswH + bbase + tid*4);
        float4 rL = *(const float4*)(g_EswL + bbase + tid*4);

#pragma unroll
        for (int kt=0; kt<16; kt++){
            int buf = kt & 1;
            *(float4*)&sBH[buf*1024 + tid*4] = rH;
            *(float4*)&sBL[buf*1024 + tid*4] = rL;
            __syncthreads();
            if (kt < 15){
                size_t nb = bbase + (size_t)(kt+1)*65536;
                rH = *(const float4*)(g_EswH + nb + tid*4);
                rL = *(const float4*)(g_EswL + nb + tid*4);
            }
            int ab = (wr+g)*TP + kt*8 + q;
            unsigned ah0 = __float_as_uint(sAh[ab]);
            unsigned ah1 = __float_as_uint(sAh[ab + 8*TP]);
            unsigned ah2 = __float_as_uint(sAh[ab + 4]);
            unsigned ah3 = __float_as_uint(sAh[ab + 8*TP + 4]);
            unsigned al0 = __float_as_uint(sAl[ab]);
            unsigned al1 = __float_as_uint(sAl[ab + 8*TP]);
            unsigned al2 = __float_as_uint(sAl[ab + 4]);
            unsigned al3 = __float_as_uint(sAl[ab + 8*TP + 4]);
            const u64* bh = (const u64*)&sBH[buf*1024] + vh*256 + lane;
            const u64* bl = (const u64*)&sBL[buf*1024] + vh*256 + lane;
#pragma unroll
            for (int j=0;j<8;j++){
                u64 hp = bh[j*32];
                u64 lp = bl[j*32];
                unsigned bh0 = (unsigned)hp, bh1 = (unsigned)(hp >> 32);
                unsigned bl0 = (unsigned)lp, bl1 = (unsigned)(lp >> 32);
                MMA4(acc[j], ah0,ah1,ah2,ah3, bh0,bh1);   // hi*hi
                MMA4(acc[j], ah0,ah1,ah2,ah3, bl0,bl1);   // hi*lo
                MMA4(acc[j], al0,al1,al2,al3, bh0,bh1);   // lo*hi
            }
        }

        // epilogue: keys from scores
#pragma unroll
        for (int j=0;j<8;j++){
            int vb = v0 + vh*64 + j*8 + 2*q;
            float2 eq = *(const float2*)&g_esq[vb];
            float s00 = fmaf(-2.f, acc[j][0], eq.x);
            float s01 = fmaf(-2.f, acc[j][1], eq.y);
            float s10 = fmaf(-2.f, acc[j][2], eq.x);
            float s11 = fmaf(-2.f, acc[j][3], eq.y);
            u64 k00 = mkkey(s00, vb),   k01 = mkkey(s01, vb+1);
            u64 k10 = mkkey(s10, vb),   k11 = mkkey(s11, vb+1);
            if (k00 < best0) best0 = k00;
            if (k01 < best0) best0 = k01;
            if (k10 < best1) best1 = k10;
            if (k11 < best1) best1 = k11;
        }
    }

    // quad reduce (lanes with same rows differ only in q bits 0..1)
    u64 t;
    t = __shfl_xor_sync(0xffffffffu, best0, 1); if (t < best0) best0 = t;
    t = __shfl_xor_sync(0xffffffffu, best0, 2); if (t < best0) best0 = t;
    t = __shfl_xor_sync(0xffffffffu, best1, 1); if (t < best1) best1 = t;
    t = __shfl_xor_sync(0xffffffffu, best1, 2); if (t < best1) best1 = t;
    if (q == 0){
        atomicMin(&sMin[wr + g],     best0);
        atomicMin(&sMin[wr + g + 8], best1);
    }
    __syncthreads();
    if (tid < 64) atomicMin(&g_keys[n0 + tid], sMin[tid]);
}

// ---------------- staged gather for pn in {1,2,4,8} ----------------
__global__ __launch_bounds__(256) void k_gather_s(const float* __restrict__ E, int pn, int woff){
    __shared__ float sE[64][16];
    __shared__ int sIdx[64];
    int b = blockIdx.x, cg = blockIdx.y;
    int c0 = cg*16;
    int tid = threadIdx.x;
    int nn = pn*pn;
    if (tid < nn) sIdx[tid] = (int)(unsigned)(g_keys[b*nn + tid]);
    __syncthreads();
    for (int r0 = 0; r0 < nn; r0 += 16){
        int r = r0 + (tid >> 4), cl = tid & 15;
        if (r < nn) sE[r][cl] = E[(size_t)sIdx[r]*C_ + c0 + cl];
    }
    __syncthreads();
    int pix = tid, o1 = pix >> 4, o2 = pix & 15;
#pragma unroll 4
    for (int c=0;c<16;c++){
        float acc = 0.f;
        for (int i1=0;i1<pn;i1++){
            float w1 = g_W[woff + o1*pn + i1];
            if (w1 == 0.f) continue;
            for (int i2=0;i2<pn;i2++){
                float w2 = g_W[woff + o2*pn + i2];
                if (w2 == 0.f) continue;
                acc = fmaf(w1*w2, sE[i1*pn+i2][c], acc);
            }
        }
        g_hup[((size_t)b*C_ + c0 + c)*HW_ + pix] = acc;
    }
}

// ---------------- direct gather for pn=16 ----------------
__global__ void k_gather(const float* __restrict__ E){
    int bp = blockIdx.x; int b = bp >> 8; int pix = bp & 255;
    int c = threadIdx.x;   // 128
    int v = (int)(unsigned)(g_keys[b*256 + pix]);
    g_hup[(b*C_ + c)*HW_ + pix] = E[(size_t)v*C_ + c];
}

// ---------------- conv3x3 (f32x2 taps) + Phi + updates + next-stage key init ----------------
__global__ __launch_bounds__(256,2) void k_conv(
    const float* __restrict__ phiw, const float* __restrict__ phib,
    const float* __restrict__ f, float* __restrict__ fhat,
    int kphi, int si, int Nn)
{
    __shared__ __align__(16) float sIn[16][256];
    __shared__ __align__(16) float sW[16][16][12];
    __shared__ float sRed[256];
    int b = blockIdx.x, ocg = blockIdx.y;
    int tid = threadIdx.x;
    int ocl = tid >> 4, h = tid & 15;
    int oc = ocg*16 + ocl;

    if (Nn > 0){
        int flat = b*8 + ocg;                 // 0..255
        int per = (Nn + 255) >> 8;
        if (tid < per){
            int ki = flat*per + tid;
            if (ki < Nn) g_keys[ki] = ~0ull;
        }
    }

    u64 acc2[8];
#pragma unroll
    for (int m=0;m<8;m++) acc2[m]=0ull;

    const float* inb = g_hup + (size_t)b*C_*HW_;
    for (int icc=0; icc<128; icc+=16){
#pragma unroll
        for (int t=0;t<16;t++)
            sIn[t][tid] = inb[(icc+t)*HW_ + tid];
        {
            const float* wp = phiw + (((size_t)kphi*C_ + oc)*C_ + (icc + h))*9;
#pragma unroll
            for (int k=0;k<9;k++) sW[h][ocl][k] = wp[k];
        }
        __syncthreads();
        for (int ic=0; ic<16; ic++){
            float4 wa = *(const float4*)&sW[ic][ocl][0];
            float4 wb = *(const float4*)&sW[ic][ocl][4];
            float w8 = sW[ic][ocl][8];
            float wf[9] = {wa.x,wa.y,wa.z,wa.w,wb.x,wb.y,wb.z,wb.w,w8};
            u64 w2[9];
#pragma unroll
            for (int t=0;t<9;t++) w2[t] = pk2(wf[t], wf[t]);

            u64 s2[8];
#pragma unroll
            for (int m=0;m<8;m++) s2[m]=0ull;

#pragma unroll
            for (int dh=0; dh<3; dh++){
                int hh = h + dh - 1;
                u64 O[8], Ep[9];
                if (hh >= 0 && hh < 16){
                    F4U l0,l1,l2,l3;
                    const float4* rp = (const float4*)&sIn[ic][hh*16];
                    l0.f = rp[0]; l1.f = rp[1]; l2.f = rp[2]; l3.f = rp[3];
                    O[0]=l0.u[0]; O[1]=l0.u[1]; O[2]=l1.u[0]; O[3]=l1.u[1];
                    O[4]=l2.u[0]; O[5]=l2.u[1]; O[6]=l3.u[0]; O[7]=l3.u[1];
                    Ep[0]=pk2(0.f,   l0.f.x); Ep[1]=pk2(l0.f.y, l0.f.z);
                    Ep[2]=pk2(l0.f.w, l1.f.x); Ep[3]=pk2(l1.f.y, l1.f.z);
                    Ep[4]=pk2(l1.f.w, l2.f.x); Ep[5]=pk2(l2.f.y, l2.f.z);
                    Ep[6]=pk2(l2.f.w, l3.f.x); Ep[7]=pk2(l3.f.y, l3.f.z);
                    Ep[8]=pk2(l3.f.w, 0.f);
                } else {
#pragma unroll
                    for (int m=0;m<8;m++) O[m]=0ull;
#pragma unroll
                    for (int m=0;m<9;m++) Ep[m]=0ull;
                }
#pragma unroll
                for (int m=0;m<8;m++){
                    fma2(s2[m], Ep[m],   w2[dh*3+0]);   // dw=0
                    fma2(s2[m], O[m],    w2[dh*3+1]);   // dw=1
                    fma2(s2[m], Ep[m+1], w2[dh*3+2]);   // dw=2
                }
            }
#pragma unroll
            for (int m=0;m<8;m++) add2(acc2[m], s2[m]);
        }
        __syncthreads();
    }

    float acc[16];
#pragma unroll
    for (int m=0;m<8;m++) upk2(acc[2*m], acc[2*m+1], acc2[m]);

    float bias = phib[kphi*C_ + oc];
    int base = (b*C_ + oc)*HW_ + h*16;
    float lsum = 0.f;
#pragma unroll
    for (int x=0;x<16;x++){
        float y  = acc[x] + bias;
        float hi = g_hup[base + x];
        float hp = 0.5f*hi + 0.5f*y;          // Phi: x*(1-r) + conv(x)*r, r=0.5
        float fh = fhat[base + x] + hp;
        fhat[base + x] = fh;
        g_frest[base + x] -= hp;
        float d = fh - f[base + x];
        lsum = fmaf(d, d, lsum);
    }
    sRed[tid] = lsum;
    __syncthreads();
    for (int s=128; s>0; s>>=1){
        if (tid < s) sRed[tid] += sRed[tid+s];
        __syncthreads();
    }
    if (tid == 0) g_lossPart[si*256 + ocg*32 + b] = sRed[0];
}

// ---------------- loss finalize (deterministic, double) ----------------
__global__ void k_final(float* out){
    if (threadIdx.x == 0){
        double total = 0.0;
        for (int s=0;s<5;s++){
            double m = 0.0;
            for (int i=0;i<256;i++) m += (double)g_lossPart[s*256+i];
            total += 1.25 * (m / (double)TOT);   // (1+BETA)*mean
        }
        out[TOT] = (float)(total / 5.0);          // / SN
    }
}

// ---------------- launch ----------------
extern "C" void kernel_launch(void* const* d_in, const int* in_sizes, int n_in,
                              void* d_out, int out_size){
    (void)in_sizes; (void)n_in; (void)out_size;
    const float* f  = (const float*)d_in[0];
    const float* E  = (const float*)d_in[1];
    const float* pw = (const float*)d_in[2];
    const float* pb = (const float*)d_in[3];
    float* out = (float*)d_out;

    // replicate np.linspace(1/12, 11/12, 4) + argmin tick selection in double
    double start = 1.0/12.0, stop = 1.0 - 1.0/12.0;
    double step = (stop - start) / 3.0;
    double ticks[4];
    for (int i=0;i<4;i++) ticks[i] = (double)i*step + start;
    ticks[3] = stop;
    int kphi[5];
    for (int si=0;si<5;si++){
        double t = (double)si / 4.0;
        int best = 0;
        for (int k=1;k<4;k++)
            if (fabs(ticks[k]-t) < fabs(ticks[best]-t)) best = k;
        kphi[si] = best;
    }

    const int DYN2 = 128*TP*4 + 4*2048*4 + 64*8;   // 84480 bytes
    cudaFuncSetAttribute(k_argmin_t, cudaFuncAttributeMaxDynamicSharedMemorySize, DYN2);

    k_init<<<512, 256>>>(f, out);
    k_esq<<<V_, 128>>>(E);
    k_split<<<4096, 256>>>(E);

    // stage 0: pn=1, N=32
    k_pool<<<B_*C_, 256>>>(1);
    k_argmin_s<<<dim3(1,64), 256>>>(E, 128);
    k_gather_s<<<dim3(B_,8), 256>>>(E, 1, 0);
    k_conv<<<dim3(B_,8), 256>>>(pw, pb, f, out, kphi[0], 0, 128);

    // stage 1: pn=2, N=128
    k_pool<<<B_*C_, 256>>>(2);
    k_argmin_s<<<dim3(4,64), 256>>>(E, 128);
    k_gather_s<<<dim3(B_,8), 256>>>(E, 2, 16);
    k_conv<<<dim3(B_,8), 256>>>(pw, pb, f, out, kphi[1], 1, 512);

    // stage 2: pn=4, N=512 (tensor argmin)
    k_pool<<<B_*C_, 256>>>(4);
    k_argmin_t<<<dim3(8,32), 256, DYN2>>>(256, 0);
    k_gather_s<<<dim3(B_,8), 256>>>(E, 4, 48);
    k_conv<<<dim3(B_,8), 256>>>(pw, pb, f, out, kphi[2], 2, 2048);

    // stage 3: pn=8, N=2048 (tensor argmin)
    k_pool<<<B_*C_, 256>>>(8);
    k_argmin_t<<<dim3(32,8), 256, DYN2>>>(1024, 0);
    k_gather_s<<<dim3(B_,8), 256>>>(E, 8, 112);
    k_conv<<<dim3(B_,8), 256>>>(pw, pb, f, out, kphi[3], 3, 8192);

    // stage 4: pn=16, N=8192 (tensor argmin, rows directly from g_frest)
    k_argmin_t<<<dim3(128,2), 256, DYN2>>>(4096, 1);
    k_gather<<<B_*HW_, 128>>>(E);
    k_conv<<<dim3(B_,8), 256>>>(pw, pb, f, out, kphi[4], 4, 0);

    k_final<<<1, 32>>>(out);
}